// round 4
// baseline (speedup 1.0000x reference)
#include <cuda_runtime.h>

// FilteringActLayer fused per-tile kernel, v4.
// Pipeline: bias -> UH -> UW -> act -> DH -> DW.  Since DH and DW are linear
// and both after the pointwise act, they commute:  out = DH(DW(act(UW(UH x)))).
// So we fuse UW+act+DW into one per-row register pass, eliminating the 74x74
// intermediate entirely.  Polyphase even/odd outputs share data operands, so
// they are computed pairwise with packed fma.rn.f32x2.
//
// smem chain per 32x32 output tile:
//   xs 42x42 (stride 43, in bufA) --UH--> t1 74x42 (stride 43)
//   --UW+act+DW (registers)--> z 74x32 (stride 33, aliases bufA)
//   --DH--> out 32x32 (gmem).
// Odd strides 43/33 => conflict-free cross-lane LDS.

#define TS 32
typedef unsigned long long ull;

__device__ __forceinline__ ull pk2(float a, float b) {
    ull r; asm("mov.b64 %0, {%1, %2};" : "=l"(r) : "f"(a), "f"(b)); return r;
}
__device__ __forceinline__ void upk2(ull v, float& a, float& b) {
    asm("mov.b64 {%0, %1}, %2;" : "=f"(a), "=f"(b) : "l"(v));
}
__device__ __forceinline__ ull ffma2(ull a, ull b, ull c) {
    ull d; asm("fma.rn.f32x2 %0, %1, %2, %3;" : "=l"(d) : "l"(a), "l"(b), "l"(c));
    return d;
}

__global__ __launch_bounds__(256, 4)
void filt_act_kernel(const float* __restrict__ x,
                     const float* __restrict__ b,
                     const float* __restrict__ upf,
                     const float* __restrict__ dnf,
                     const float* __restrict__ gainp,
                     const float* __restrict__ slopep,
                     const float* __restrict__ clampp,
                     float* __restrict__ out)
{
    __shared__ float bufA[2442];          // xs (<=1934 incl. junk row) | z 74*33
    __shared__ float t1[74 * 43];         // 3182
    __shared__ float sU0[6], sU1[6], sD[12], sPar[4];

    const int tid   = threadIdx.x;
    const int plane = blockIdx.z;                  // n*128 + c
    const int R0    = blockIdx.y * TS;
    const int C0    = blockIdx.x * TS;
    const float* __restrict__ xp = x   + (size_t)plane * 128 * 128;
    float*       __restrict__ op = out + (size_t)plane * 128 * 128;

    if (tid < 6)        sU0[tid]     = 2.0f * upf[2 * tid + 1];   // even parity
    else if (tid < 12)  sU1[tid - 6] = 2.0f * upf[2 * (tid - 6)]; // odd parity
    else if (tid < 24)  sD[tid - 12] = dnf[tid - 12];
    else if (tid == 24) {
        sPar[0] = b[plane & 127];
        sPar[1] = *gainp;
        sPar[2] = *slopep;
        sPar[3] = *clampp;
    }
    __syncthreads();

    const float bias  = sPar[0];
    const float gain  = sPar[1];
    const float slope = sPar[2];
    const float clmp  = sPar[3];

    // packed polyphase taps (even parity in lo, odd in hi)
    ull uP[6];
    #pragma unroll
    for (int d = 0; d < 6; d++) uP[d] = pk2(sU0[d], sU1[d]);
    float fd[12];
    #pragma unroll
    for (int k = 0; k < 12; k++) fd[k] = sD[k];

    // ---- stage 0: load 44x42 input patch (+bias, zero outside) ----
    float* xs = bufA;
    #pragma unroll
    for (int it = 0; it < 8; it++) {
        int idx = tid + it * 256;
        if (idx < 1848) {                          // 44*42
            int r  = idx / 42;
            int cc = idx - r * 42;
            int gr = R0 - 5 + r;
            int gc = C0 - 5 + cc;
            float v = 0.0f;
            if ((unsigned)gr < 128u && (unsigned)gc < 128u)
                v = xp[gr * 128 + gc] + bias;
            xs[r * 43 + cc] = v;
        }
    }
    __syncthreads();

    // ---- stage 1: upsample H (packed parities). 210 threads ----
    if (tid < 210) {
        int g  = tid / 42;              // 0..4
        int cc = tid - 42 * g;
        const float* p = &xs[(8 * g) * 43 + cc];
        ull w2[13];
        #pragma unroll
        for (int d = 0; d < 13; d++) { float wv = p[d * 43]; w2[d] = pk2(wv, wv); }
        #pragma unroll
        for (int s = 0; s < 4; s++) {
            int row0 = 16 * g + 4 * s;
            ull aA = 0ull, aB = 0ull;
            #pragma unroll
            for (int d = 0; d < 6; d++) {
                aA = ffma2(uP[d], w2[2 * s + d],     aA);
                aB = ffma2(uP[d], w2[2 * s + d + 1], aB);
            }
            float o0, o1, o2, o3;
            upk2(aA, o0, o1);
            upk2(aB, o2, o3);
            float* q = &t1[row0 * 43 + cc];
            if (row0 < 74)     q[0]   = o0;
            if (row0 + 1 < 74) q[43]  = o1;
            if (row0 + 2 < 74) q[86]  = o2;
            if (row0 + 3 < 74) q[129] = o3;
        }
    }
    __syncthreads();

    // ---- stage B: per-row UW + act + DW, all in registers ----
    // 296 items: item = (chunk c in 0..3) * 74 + row i.  Each item produces
    // z[i][8c..8c+7] from t1[i][8c..8c+17].
    float* z = bufA;    // xs dead
    #pragma unroll
    for (int pass = 0; pass < 2; pass++) {
        int id = tid + pass * 256;
        if (id < 296) {
            int c = id / 74;
            int i = id - 74 * c;
            const float* p = &t1[i * 43 + 8 * c];
            float zr[8];
            #pragma unroll
            for (int ol = 0; ol < 8; ol++) zr[ol] = 0.0f;

            ull w2[18];
            #pragma unroll
            for (int d = 0; d < 5; d++) { float wv = p[d]; w2[d] = pk2(wv, wv); }

            #pragma unroll
            for (int m = 0; m < 13; m++) {
                { float wv = p[m + 5]; w2[m + 5] = pk2(wv, wv); }
                ull acc = 0ull;
                #pragma unroll
                for (int d = 0; d < 6; d++)
                    acc = ffma2(uP[d], w2[m + d], acc);
                float ae, ao;
                upk2(acc, ae, ao);
                // activation (lrelu * gain, clamp)
                ae = (ae >= 0.f ? ae : ae * slope) * gain;
                ao = (ao >= 0.f ? ao : ao * slope) * gain;
                ae = fminf(fmaxf(ae, -clmp), clmp);
                ao = fminf(fmaxf(ao, -clmp), clmp);
                // scatter into the 8 down-W accumulators:
                // A[16c + j] feeds z[8c+ol] with tap fd[j-2*ol]
                const int j0 = 2 * m, j1 = 2 * m + 1;
                #pragma unroll
                for (int ol = 0; ol < 8; ol++) {
                    int k0 = j0 - 2 * ol;
                    int k1 = j1 - 2 * ol;
                    if (k0 >= 0 && k0 < 12) zr[ol] = fmaf(fd[k0], ae, zr[ol]);
                    if (k1 >= 0 && k1 < 12) zr[ol] = fmaf(fd[k1], ao, zr[ol]);
                }
            }
            float* q = &z[i * 33 + 8 * c];
            #pragma unroll
            for (int ol = 0; ol < 8; ol++) q[ol] = zr[ol];
        }
    }
    __syncthreads();

    // ---- stage 3: downsample H + store. 256 threads, 4 outputs each ----
    {
        int col = tid & 31;
        int g   = tid >> 5;             // 0..7 -> outputs 4g..4g+3
        const float* p = &z[(8 * g) * 33 + col];
        float w[18];
        #pragma unroll
        for (int j = 0; j < 18; j++) w[j] = p[j * 33];
        #pragma unroll
        for (int m = 0; m < 4; m++) {
            float acc = 0.f;
            #pragma unroll
            for (int k = 0; k < 12; k++)
                acc = fmaf(fd[k], w[2 * m + k], acc);
            op[(R0 + 4 * g + m) * 128 + C0 + col] = acc;
        }
    }
}

extern "C" void kernel_launch(void* const* d_in, const int* in_sizes, int n_in,
                              void* d_out, int out_size)
{
    const float* x     = (const float*)d_in[0];
    const float* b     = (const float*)d_in[1];
    const float* upf   = (const float*)d_in[2];
    const float* dnf   = (const float*)d_in[3];
    const float* gain  = (const float*)d_in[4];
    const float* slope = (const float*)d_in[5];
    const float* clmp  = (const float*)d_in[6];
    float* out = (float*)d_out;

    dim3 grid(128 / TS, 128 / TS, 8 * 128);   // (4,4,1024)
    filt_act_kernel<<<grid, 256>>>(x, b, upf, dnf, gain, slope, clmp, out);
}

// round 5
// speedup vs baseline: 1.1351x; 1.1351x over previous
#include <cuda_runtime.h>

// FilteringActLayer fused per-tile kernel, v5.
// out = DH( DW( act( UW( UH(x + b) ) ) ) )   (DH/DW commute past each other)
// Stage B fuses UW + act + DW per row in registers: no 74x74 intermediate.
// All scalar FMA (f32x2 packing removed: MOV-pack cost > FMA savings).
// act uses max-trick: lrelu(x)*g = max(g*x, g*s*x)  (g>0, 0<s<1).
// gain is folded into the W-pass upsample taps.
//
// smem chain per 32x32 output tile:
//   xs 44x42 (stride 43, bufA) --UH--> t1 74x42 (stride 43)
//   --UW+act+DW (regs)--> z 74x32 (stride 33, aliases bufA) --DH--> gmem.

#define TS 32

__global__ __launch_bounds__(256, 4)
void filt_act_kernel(const float* __restrict__ x,
                     const float* __restrict__ b,
                     const float* __restrict__ upf,
                     const float* __restrict__ dnf,
                     const float* __restrict__ gainp,
                     const float* __restrict__ slopep,
                     const float* __restrict__ clampp,
                     float* __restrict__ out)
{
    __shared__ float bufA[2442];          // xs 44*43=1892 | z 74*33=2442
    __shared__ float t1[74 * 43];         // 3182
    __shared__ float sU0[6], sU1[6], sD[12], sPar[4];

    const int tid   = threadIdx.x;
    const int plane = blockIdx.z;                  // n*128 + c
    const int R0    = blockIdx.y * TS;
    const int C0    = blockIdx.x * TS;
    const float* __restrict__ xp = x   + (size_t)plane * 128 * 128;
    float*       __restrict__ op = out + (size_t)plane * 128 * 128;

    if (tid < 6)        sU0[tid]     = 2.0f * upf[2 * tid + 1];   // even parity
    else if (tid < 12)  sU1[tid - 6] = 2.0f * upf[2 * (tid - 6)]; // odd parity
    else if (tid < 24)  sD[tid - 12] = dnf[tid - 12];
    else if (tid == 24) {
        sPar[0] = b[plane & 127];
        sPar[1] = *gainp;
        sPar[2] = *slopep;
        sPar[3] = *clampp;
    }
    __syncthreads();

    const float bias  = sPar[0];
    const float gain  = sPar[1];
    const float slope = sPar[2];
    const float clmp  = sPar[3];

    // ---- stage 0: load 44x42 input patch (+bias, zero outside) ----
    float* xs = bufA;
    #pragma unroll
    for (int it = 0; it < 8; it++) {
        int idx = tid + it * 256;
        if (idx < 1848) {                          // 44*42
            int r  = idx / 42;
            int cc = idx - r * 42;
            int gr = R0 - 5 + r;
            int gc = C0 - 5 + cc;
            float v = 0.0f;
            if ((unsigned)gr < 128u && (unsigned)gc < 128u)
                v = xp[gr * 128 + gc] + bias;
            xs[r * 43 + cc] = v;
        }
    }
    __syncthreads();

    float u0[6], u1[6];
    #pragma unroll
    for (int d = 0; d < 6; d++) { u0[d] = sU0[d]; u1[d] = sU1[d]; }

    // ---- stage 1: upsample H (scalar). 210 threads: col cc, 4 j0p each ----
    if (tid < 210) {
        int g  = tid / 42;              // 0..4
        int cc = tid - 42 * g;
        const float* p = &xs[(8 * g) * 43 + cc];
        float w[13];
        #pragma unroll
        for (int d = 0; d < 13; d++) w[d] = p[d * 43];
        #pragma unroll
        for (int s = 0; s < 4; s++) {
            int row0 = 16 * g + 4 * s;
            float o0 = 0.f, o1 = 0.f, o2 = 0.f, o3 = 0.f;
            #pragma unroll
            for (int d = 0; d < 6; d++) {
                float wa = w[2 * s + d], wb = w[2 * s + d + 1];
                o0 = fmaf(u0[d], wa, o0);
                o1 = fmaf(u1[d], wa, o1);
                o2 = fmaf(u0[d], wb, o2);
                o3 = fmaf(u1[d], wb, o3);
            }
            float* q = &t1[row0 * 43 + cc];
            if (row0 < 74)     q[0]   = o0;
            if (row0 + 1 < 74) q[43]  = o1;
            if (row0 + 2 < 74) q[86]  = o2;
            if (row0 + 3 < 74) q[129] = o3;
        }
    }
    __syncthreads();

    // gain-folded W-pass taps; down taps
    float u0g[6], u1g[6], fd[12];
    #pragma unroll
    for (int d = 0; d < 6; d++) { u0g[d] = u0[d] * gain; u1g[d] = u1[d] * gain; }
    #pragma unroll
    for (int k = 0; k < 12; k++) fd[k] = sD[k];

    // ---- stage B: per-half-row UW + act + DW in registers. 148 items ----
    // item (h,i): z[i][16h..16h+15] from t1[i][16h..16h+25].
    float* z = bufA;    // xs dead
    if (tid < 148) {
        int h = tid / 74;               // 0 or 1
        int i = tid - 74 * h;
        const float* p = &t1[i * 43 + 16 * h];

        float acc[16];
        #pragma unroll
        for (int ol = 0; ol < 16; ol++) acc[ol] = 0.0f;

        float wr[6];
        #pragma unroll
        for (int d = 0; d < 5; d++) wr[d] = p[d];

        #pragma unroll
        for (int m = 0; m < 21; m++) {
            wr[(m + 5) % 6] = p[m + 5];
            float ae = 0.f, ao = 0.f;
            #pragma unroll
            for (int d = 0; d < 6; d++) {
                float wv = wr[(m + d) % 6];
                ae = fmaf(u0g[d], wv, ae);
                ao = fmaf(u1g[d], wv, ao);
            }
            // act: lrelu*gain (gain already folded) via max, then clamp
            ae = fmaxf(ae, ae * slope);
            ao = fmaxf(ao, ao * slope);
            ae = fmaxf(fminf(ae, clmp), -clmp);
            ao = fmaxf(fminf(ao, clmp), -clmp);
            // scatter: local A indices 2m, 2m+1 feed acc[ol] with taps
            // fd[2m-2ol], fd[2m+1-2ol] when in [0,12)
            #pragma unroll
            for (int ol = 0; ol < 16; ol++) {
                const int k0 = 2 * m - 2 * ol;
                if (k0 >= 0 && k0 < 12) {
                    acc[ol] = fmaf(fd[k0],     ae, acc[ol]);
                    acc[ol] = fmaf(fd[k0 + 1], ao, acc[ol]);
                }
            }
        }
        float* q = &z[i * 33 + 16 * h];
        #pragma unroll
        for (int ol = 0; ol < 16; ol++) q[ol] = acc[ol];
    }
    __syncthreads();

    // ---- stage 3: downsample H + store. 256 threads, 4 outputs each ----
    {
        int col = tid & 31;
        int g   = tid >> 5;             // 0..7 -> output rows 4g..4g+3
        const float* p = &z[(8 * g) * 33 + col];
        float w[18];
        #pragma unroll
        for (int j = 0; j < 18; j++) w[j] = p[j * 33];
        #pragma unroll
        for (int m = 0; m < 4; m++) {
            float acc = 0.f;
            #pragma unroll
            for (int k = 0; k < 12; k++)
                acc = fmaf(fd[k], w[2 * m + k], acc);
            op[(R0 + 4 * g + m) * 128 + C0 + col] = acc;
        }
    }
}

extern "C" void kernel_launch(void* const* d_in, const int* in_sizes, int n_in,
                              void* d_out, int out_size)
{
    const float* x     = (const float*)d_in[0];
    const float* b     = (const float*)d_in[1];
    const float* upf   = (const float*)d_in[2];
    const float* dnf   = (const float*)d_in[3];
    const float* gain  = (const float*)d_in[4];
    const float* slope = (const float*)d_in[5];
    const float* clmp  = (const float*)d_in[6];
    float* out = (float*)d_out;

    dim3 grid(128 / TS, 128 / TS, 8 * 128);   // (4,4,1024)
    filt_act_kernel<<<grid, 256>>>(x, b, upf, dnf, gain, slope, clmp, out);
}

// round 6
// speedup vs baseline: 1.4814x; 1.3050x over previous
#include <cuda_runtime.h>

// FilteringActLayer fused per-tile kernel, v6.
// out = DH( DW( act( UW( UH(x + b) ) ) ) ).  Stage B fuses UW+act+DW per row.
// Tile 64 rows x 32 cols of output per block (8192 blocks).
// Filter symmetry (firwin): u1[d] = u0[5-d], fd[k] = fd[11-k] -> 12 tap regs.
// All stages sized to keep ~all 256 threads busy.
//
// smem chain:
//   xs 78x42 (stride 43, bufA) --UH--> t1 138x42 (stride 43)
//   --UW+act+DW (regs)--> z 138x32 (stride 33, aliases bufA) --DH--> gmem.

#define TW 32
#define TH 64

__global__ __launch_bounds__(256, 5)
void filt_act_kernel(const float* __restrict__ x,
                     const float* __restrict__ b,
                     const float* __restrict__ upf,
                     const float* __restrict__ dnf,
                     const float* __restrict__ gainp,
                     const float* __restrict__ slopep,
                     const float* __restrict__ clampp,
                     float* __restrict__ out)
{
    __shared__ float bufA[138 * 33];      // xs 78*43=3354 | z 138*33=4554
    __shared__ float t1[138 * 43];        // 5934
    __shared__ float sU0[6], sD[6], sPar[4];

    const int tid   = threadIdx.x;
    const int plane = blockIdx.z;                  // n*128 + c
    const int R0    = blockIdx.y * TH;
    const int C0    = blockIdx.x * TW;
    const float* __restrict__ xp = x   + (size_t)plane * 128 * 128;
    float*       __restrict__ op = out + (size_t)plane * 128 * 128;

    if (tid < 6)        sU0[tid]    = 2.0f * upf[2 * tid + 1];  // even-parity taps
    else if (tid < 12)  sD[tid - 6] = dnf[tid - 6];             // fd[0..5] (symmetric)
    else if (tid == 12) {
        sPar[0] = b[plane & 127];
        sPar[1] = *gainp;
        sPar[2] = *slopep;
        sPar[3] = *clampp;
    }
    __syncthreads();

    const float bias  = sPar[0];
    const float gain  = sPar[1];
    const float slope = sPar[2];
    const float clmp  = sPar[3];

    // ---- stage 0: load 78x42 input patch (+bias, zero outside) ----
    // 252 threads: col cc fixed, rows r0, r0+6, ..., 13 rows each.
    float* xs = bufA;
    if (tid < 252) {
        int r0 = tid / 42;              // 0..5
        int cc = tid - 42 * r0;
        int gc = C0 - 5 + cc;
        bool cok = (unsigned)gc < 128u;
        #pragma unroll
        for (int k = 0; k < 13; k++) {
            int r  = r0 + 6 * k;
            int gr = R0 - 5 + r;
            float v = 0.0f;
            if (cok && (unsigned)gr < 128u)
                v = xp[gr * 128 + gc] + bias;
            xs[r * 43 + cc] = v;
        }
    }
    __syncthreads();

    float u0[6];
    #pragma unroll
    for (int d = 0; d < 6; d++) u0[d] = sU0[d];

    // ---- stage 1: upsample H. 252 threads: col cc, 6 j0p-steps each ----
    if (tid < 252) {
        int g  = tid / 42;              // 0..5 -> j0p = 6g+s
        int cc = tid - 42 * g;
        const float* p = &xs[(12 * g) * 43 + cc];
        float w[17];
        #pragma unroll
        for (int d = 0; d < 17; d++) w[d] = p[d * 43];
        #pragma unroll
        for (int s = 0; s < 6; s++) {
            int row0 = 24 * g + 4 * s;         // = 4*j0p
            float o0 = 0.f, o1 = 0.f, o2 = 0.f, o3 = 0.f;
            #pragma unroll
            for (int d = 0; d < 6; d++) {
                float wa = w[2 * s + d], wb = w[2 * s + d + 1];
                o0 = fmaf(u0[d],     wa, o0);
                o1 = fmaf(u0[5 - d], wa, o1);
                o2 = fmaf(u0[d],     wb, o2);
                o3 = fmaf(u0[5 - d], wb, o3);
            }
            float* q = &t1[row0 * 43 + cc];
            if (row0 < 138)     q[0]   = o0;
            if (row0 + 1 < 138) q[43]  = o1;
            if (row0 + 2 < 138) q[86]  = o2;
            if (row0 + 3 < 138) q[129] = o3;
        }
    }
    __syncthreads();

    // gain-folded W-pass taps; symmetric down taps
    float u0g[6], fdr[6];
    #pragma unroll
    for (int d = 0; d < 6; d++) { u0g[d] = u0[d] * gain; fdr[d] = sD[d]; }
    #define FD(k) fdr[(k) < 6 ? (k) : 11 - (k)]

    // ---- stage B: per-half-row UW + act + DW in registers. 276 items ----
    // item (h,i): z[i][16h..16h+15] from t1[i][16h..16h+25].
    float* z = bufA;    // xs dead
    #pragma unroll
    for (int pass = 0; pass < 2; pass++) {
        int id = tid + pass * 256;
        if (id < 276) {
            int h = (id >= 138) ? 1 : 0;
            int i = id - 138 * h;
            const float* p = &t1[i * 43 + 16 * h];

            float acc[16];
            #pragma unroll
            for (int ol = 0; ol < 16; ol++) acc[ol] = 0.0f;

            float wr[6];
            #pragma unroll
            for (int d = 0; d < 5; d++) wr[d] = p[d];

            #pragma unroll
            for (int m = 0; m < 21; m++) {
                wr[(m + 5) % 6] = p[m + 5];
                float ae = 0.f, ao = 0.f;
                #pragma unroll
                for (int d = 0; d < 6; d++) {
                    float wv = wr[(m + d) % 6];
                    ae = fmaf(u0g[d],     wv, ae);
                    ao = fmaf(u0g[5 - d], wv, ao);
                }
                ae = fmaxf(ae, ae * slope);
                ao = fmaxf(ao, ao * slope);
                ae = fmaxf(fminf(ae, clmp), -clmp);
                ao = fmaxf(fminf(ao, clmp), -clmp);
                #pragma unroll
                for (int ol = 0; ol < 16; ol++) {
                    const int k0 = 2 * m - 2 * ol;
                    if (k0 >= 0 && k0 < 12) {
                        acc[ol] = fmaf(FD(k0),     ae, acc[ol]);
                        acc[ol] = fmaf(FD(k0 + 1), ao, acc[ol]);
                    }
                }
            }
            float* q = &z[i * 33 + 16 * h];
            #pragma unroll
            for (int ol = 0; ol < 16; ol++) q[ol] = acc[ol];
        }
    }
    __syncthreads();

    // ---- stage 3: downsample H + store. 256 threads x 2 groups of 4 rows ----
    {
        int col = tid & 31;
        int gg0 = tid >> 5;             // 0..7; groups gg0 and gg0+8
        #pragma unroll
        for (int half = 0; half < 2; half++) {
            int gg = gg0 + 8 * half;    // 0..15 -> out rows 4gg..4gg+3
            const float* p = &z[(8 * gg) * 33 + col];
            float w[18];
            #pragma unroll
            for (int j = 0; j < 18; j++) w[j] = p[j * 33];
            #pragma unroll
            for (int m = 0; m < 4; m++) {
                float acc = 0.f;
                #pragma unroll
                for (int k = 0; k < 12; k++)
                    acc = fmaf(FD(k), w[2 * m + k], acc);
                op[(R0 + 4 * gg + m) * 128 + C0 + col] = acc;
            }
        }
    }
    #undef FD
}

extern "C" void kernel_launch(void* const* d_in, const int* in_sizes, int n_in,
                              void* d_out, int out_size)
{
    const float* x     = (const float*)d_in[0];
    const float* b     = (const float*)d_in[1];
    const float* upf   = (const float*)d_in[2];
    const float* dnf   = (const float*)d_in[3];
    const float* gain  = (const float*)d_in[4];
    const float* slope = (const float*)d_in[5];
    const float* clmp  = (const float*)d_in[6];
    float* out = (float*)d_out;

    dim3 grid(128 / TW, 128 / TH, 8 * 128);   // (4,2,1024)
    filt_act_kernel<<<grid, 256>>>(x, b, upf, dnf, gain, slope, clmp, out);
}

// round 7
// speedup vs baseline: 1.7872x; 1.2064x over previous
#include <cuda_runtime.h>

// FilteringActLayer fused per-tile kernel, v7.
// out = DH( DW( act( UW( UH(x + b) ) ) ) ).  Tile 64x32 outputs per block.
// v7: stage-0 eliminated (S1 loads gmem directly, bias folded, coalesced);
//     SB stores + S3 loads vectorized (z stride 34, float2);
//     SB 276-item tail rebalanced via quarter-chunks.
// Filter symmetry: u1[d]=u0[5-d], fd[k]=fd[11-k].

#define TW 32
#define TH 64

#define FD(k) fdr[(k) < 6 ? (k) : 11 - (k)]

template<int NCOL>
__device__ __forceinline__ void sb_chunk(const float* __restrict__ p,
                                         float* __restrict__ q,
                                         const float* __restrict__ u0g,
                                         const float* __restrict__ fdr,
                                         float slope, float clmp)
{
    // UW + act + DW for NCOL z-columns from a (2*NCOL+10)-wide A window.
    float acc[NCOL];
    #pragma unroll
    for (int ol = 0; ol < NCOL; ol++) acc[ol] = 0.0f;

    float wr[6];
    #pragma unroll
    for (int d = 0; d < 5; d++) wr[d] = p[d];

    #pragma unroll
    for (int m = 0; m < NCOL + 5; m++) {
        wr[(m + 5) % 6] = p[m + 5];
        float ae = 0.f, ao = 0.f;
        #pragma unroll
        for (int d = 0; d < 6; d++) {
            float wv = wr[(m + d) % 6];
            ae = fmaf(u0g[d],     wv, ae);
            ao = fmaf(u0g[5 - d], wv, ao);
        }
        ae = fmaxf(ae, ae * slope);
        ao = fmaxf(ao, ao * slope);
        ae = fmaxf(fminf(ae, clmp), -clmp);
        ao = fmaxf(fminf(ao, clmp), -clmp);
        #pragma unroll
        for (int ol = 0; ol < NCOL; ol++) {
            const int k0 = 2 * m - 2 * ol;
            if (k0 >= 0 && k0 < 12) {
                acc[ol] = fmaf(FD(k0),     ae, acc[ol]);
                acc[ol] = fmaf(FD(k0 + 1), ao, acc[ol]);
            }
        }
    }
    #pragma unroll
    for (int ol = 0; ol < NCOL; ol += 2)
        *reinterpret_cast<float2*>(&q[ol]) = make_float2(acc[ol], acc[ol + 1]);
}

__global__ __launch_bounds__(256, 5)
void filt_act_kernel(const float* __restrict__ x,
                     const float* __restrict__ b,
                     const float* __restrict__ upf,
                     const float* __restrict__ dnf,
                     const float* __restrict__ gainp,
                     const float* __restrict__ slopep,
                     const float* __restrict__ clampp,
                     float* __restrict__ out)
{
    __shared__ float t1[138 * 43];        // 5934
    __shared__ float z [138 * 34];        // 4692 (even stride: float2 access)
    __shared__ float sU0[6], sD[6], sPar[4];

    const int tid   = threadIdx.x;
    const int plane = blockIdx.z;                  // n*128 + c
    const int R0    = blockIdx.y * TH;
    const int C0    = blockIdx.x * TW;
    const float* __restrict__ xp = x   + (size_t)plane * 128 * 128;
    float*       __restrict__ op = out + (size_t)plane * 128 * 128;

    if (tid < 6)        sU0[tid]    = 2.0f * upf[2 * tid + 1];  // even-parity taps
    else if (tid < 12)  sD[tid - 6] = dnf[tid - 6];             // fd[0..5] symmetric
    else if (tid == 12) {
        sPar[0] = b[plane & 127];
        sPar[1] = *gainp;
        sPar[2] = *slopep;
        sPar[3] = *clampp;
    }
    __syncthreads();

    const float bias  = sPar[0];
    const float gain  = sPar[1];
    const float slope = sPar[2];
    const float clmp  = sPar[3];

    float u0[6];
    #pragma unroll
    for (int d = 0; d < 6; d++) u0[d] = sU0[d];

    // ---- stage 1: upsample H directly from gmem. 252 threads ----
    // thread (g, cc): loads 17 rows of column C0-5+cc, emits t1 rows 24g..24g+23.
    if (tid < 252) {
        int g  = tid / 42;              // 0..5
        int cc = tid - 42 * g;
        int gc = C0 - 5 + cc;
        bool cok = (unsigned)gc < 128u;
        int rbase = R0 - 5 + 12 * g;
        float w[17];
        #pragma unroll
        for (int d = 0; d < 17; d++) {
            int gr = rbase + d;
            float v = 0.0f;
            if (cok && (unsigned)gr < 128u)
                v = xp[gr * 128 + gc] + bias;
            w[d] = v;
        }
        #pragma unroll
        for (int s = 0; s < 6; s++) {
            int row0 = 24 * g + 4 * s;
            float o0 = 0.f, o1 = 0.f, o2 = 0.f, o3 = 0.f;
            #pragma unroll
            for (int d = 0; d < 6; d++) {
                float wa = w[2 * s + d], wb = w[2 * s + d + 1];
                o0 = fmaf(u0[d],     wa, o0);
                o1 = fmaf(u0[5 - d], wa, o1);
                o2 = fmaf(u0[d],     wb, o2);
                o3 = fmaf(u0[5 - d], wb, o3);
            }
            float* q = &t1[row0 * 43 + cc];
            if (row0 < 138)     q[0]   = o0;
            if (row0 + 1 < 138) q[43]  = o1;
            if (row0 + 2 < 138) q[86]  = o2;
            if (row0 + 3 < 138) q[129] = o3;
        }
    }
    __syncthreads();

    // gain-folded W-pass taps; symmetric down taps
    float u0g[6], fdr[6];
    #pragma unroll
    for (int d = 0; d < 6; d++) { u0g[d] = u0[d] * gain; fdr[d] = sD[d]; }

    // ---- stage B: UW + act + DW per half-row. 276 half-items ----
    // pass 1: 256 full halves (h=0 rows 0..137, h=1 rows 0..117)
    {
        int h = (tid >= 138) ? 1 : 0;
        int i = tid - 138 * h;
        sb_chunk<16>(&t1[i * 43 + 16 * h], &z[i * 34 + 16 * h],
                     u0g, fdr, slope, clmp);
    }
    // pass 2: remaining 20 halves (h=1 rows 118..137) as 40 quarter-chunks
    if (tid < 40) {
        int i   = 118 + (tid >> 1);
        int sub = tid & 1;
        sb_chunk<8>(&t1[i * 43 + 16 + 8 * sub], &z[i * 34 + 16 + 8 * sub],
                    u0g, fdr, slope, clmp);
    }
    __syncthreads();

    // ---- stage 3: downsample H + store. 256 threads, 2 cols x 4 rows each ----
    {
        int cp = tid & 15;              // column pair -> cols 2cp, 2cp+1
        int gg = tid >> 4;              // 0..15 -> output rows 4gg..4gg+3
        const float* p = &z[(8 * gg) * 34 + 2 * cp];
        float2 w2[18];
        #pragma unroll
        for (int j = 0; j < 18; j++)
            w2[j] = *reinterpret_cast<const float2*>(&p[j * 34]);
        #pragma unroll
        for (int m = 0; m < 4; m++) {
            float ax = 0.f, ay = 0.f;
            #pragma unroll
            for (int k = 0; k < 12; k++) {
                ax = fmaf(FD(k), w2[2 * m + k].x, ax);
                ay = fmaf(FD(k), w2[2 * m + k].y, ay);
            }
            *reinterpret_cast<float2*>(&op[(R0 + 4 * gg + m) * 128 + C0 + 2 * cp])
                = make_float2(ax, ay);
        }
    }
}

extern "C" void kernel_launch(void* const* d_in, const int* in_sizes, int n_in,
                              void* d_out, int out_size)
{
    const float* x     = (const float*)d_in[0];
    const float* b     = (const float*)d_in[1];
    const float* upf   = (const float*)d_in[2];
    const float* dnf   = (const float*)d_in[3];
    const float* gain  = (const float*)d_in[4];
    const float* slope = (const float*)d_in[5];
    const float* clmp  = (const float*)d_in[6];
    float* out = (float*)d_out;

    dim3 grid(128 / TW, 128 / TH, 8 * 128);   // (4,2,1024)
    filt_act_kernel<<<grid, 256>>>(x, b, upf, dnf, gain, slope, clmp, out);
}